// round 14
// baseline (speedup 1.0000x reference)
#include <cuda_runtime.h>
#include <cuda_bf16.h>
#include <cstdint>
#include <math.h>

#define BB 2048
#define NN 32
#define HH 256
#define H3 768
#define ZZ 64
#define TB 16
#define NCTA (BB / TB)   // 128
#define NTHR 1024
#define PAD 20
#define CHUNK 16
#define NBUF 3
#define NCH (HH / CHUNK)             // 16 chunks per segment
#define WB_FLOATS (CHUNK * H3)       // 12288 floats = 49152 B
#define WB_BYTES  (WB_FLOATS * 4)
#define GC_FLOATS (CHUNK * HH)       // 4096 floats = 16384 B
#define GC_BYTES  (GC_FLOATS * 4)
#define TOTAL_POS (63 * 16)          // interleaved B/C chunk stream (16 chunks/segment)

// dynamic smem layout (floats)
#define OFF_WB    0
#define OFF_AGG   (OFF_WB + NBUF * WB_FLOATS)     // 36864
#define OFF_H     (OFF_AGG + HH * PAD)
#define OFF_WIH   (OFF_H + HH * PAD)
#define OFF_ADJ   (OFF_WIH + 10 * H3)
#define OFF_NT    (OFF_ADJ + TB * NN)
#define OFF_MBAR  (OFF_NT + TB)                   // even float count -> 8B aligned
#define SMEM_BYTES ((OFF_MBAR + 16) * 4 + 64)     // ~216 KB

__device__ float g_gm[BB * NN * HH];      // 64 MB
__device__ float g_adjt[BB * NN * NN];    // 8 MB

typedef unsigned long long u64;
typedef unsigned int u32;

__device__ __forceinline__ u64 pack2(float x) {
    u64 r; asm("mov.b64 %0, {%1, %1};" : "=l"(r) : "f"(x)); return r;
}
__device__ __forceinline__ void ffma2(u64 &d, u64 a, u64 b) {
    asm("fma.rn.f32x2 %0, %1, %2, %0;" : "+l"(d) : "l"(a), "l"(b));
}
__device__ __forceinline__ float2 unpack2(u64 a) {
    float2 f; asm("mov.b64 {%0, %1}, %2;" : "=f"(f.x), "=f"(f.y) : "l"(a)); return f;
}
__device__ __forceinline__ float fsig(float x) {
    return __fdividef(1.0f, 1.0f + __expf(-x));
}
__device__ __forceinline__ float ftanh(float x) {
    float y; asm("tanh.approx.f32 %0, %1;" : "=f"(y) : "f"(x)); return y;
}
__device__ __forceinline__ u32 s2u(const void* p) {
    u32 a;
    asm("{ .reg .u64 t; cvta.to.shared.u64 t, %1; cvt.u32.u64 %0, t; }" : "=r"(a) : "l"(p));
    return a;
}
__device__ __forceinline__ void mbar_init(u32 mb, u32 cnt) {
    asm volatile("mbarrier.init.shared.b64 [%0], %1;" :: "r"(mb), "r"(cnt) : "memory");
}
__device__ __forceinline__ void mbar_expect(u32 mb, u32 bytes) {
    asm volatile("mbarrier.arrive.expect_tx.shared.b64 _, [%0], %1;" :: "r"(mb), "r"(bytes) : "memory");
}
__device__ __forceinline__ void mbar_arrive(u32 mb) {
    asm volatile("mbarrier.arrive.release.cta.shared::cta.b64 _, [%0];" :: "r"(mb) : "memory");
}
__device__ __forceinline__ void bulk_cp(u32 dst, const void* src, u32 bytes, u32 mb) {
    asm volatile("cp.async.bulk.shared::cta.global.mbarrier::complete_tx::bytes [%0], [%1], %2, [%3];"
                 :: "r"(dst), "l"(src), "r"(bytes), "r"(mb) : "memory");
}
__device__ __forceinline__ void mbar_wait(u32 mb, u32 parity) {
    asm volatile("{\n\t"
                 ".reg .pred P;\n"
                 "WL%=:\n\t"
                 "mbarrier.try_wait.parity.acquire.cta.shared::cta.b64 P, [%0], %1;\n\t"
                 "@!P bra WL%=;\n\t"
                 "}" :: "r"(mb), "r"(parity) : "memory");
}

__global__ void transpose_adj_kernel(const float* __restrict__ adj) {
    int idx = blockIdx.x * blockDim.x + threadIdx.x;
    if (idx < BB * NN * NN) {
        int b = idx >> 10;
        int r = idx & 1023;
        int v = r >> 5;
        int n = r & 31;
        g_adjt[idx] = adj[(b << 10) + (n << 5) + v];
    }
}

// issue the TMA copy for global stream position `pos` into buffer `buf`
__device__ __forceinline__ void issue_copy(
    int pos, int buf, u32 wbu, u32 mb_full_base,
    const float* __restrict__ w_hh,
    const float* __restrict__ w_gate,
    const float* __restrict__ w_map)
{
    const int seg = pos >> 4;            // 16 chunks per segment
    const int rem = pos & 15;
    const u32 dst = wbu + (u32)buf * WB_BYTES;
    const u32 mb  = mb_full_base + (u32)buf * 8;
    if (seg & 1) {   // C segment: gate + map chunk
        mbar_expect(mb, 2 * GC_BYTES);
        bulk_cp(dst, w_gate + rem * GC_FLOATS, GC_BYTES, mb);
        bulk_cp(dst + GC_BYTES, w_map + rem * GC_FLOATS, GC_BYTES, mb);
    } else {         // B segment: w_hh chunk
        mbar_expect(mb, WB_BYTES);
        bulk_cp(dst, w_hh + rem * WB_FLOATS, WB_BYTES, mb);
    }
}

__global__ __launch_bounds__(NTHR, 1) void logicvae_main(
    const int*   __restrict__ node_types,
    const float* __restrict__ w_ih,
    const float* __restrict__ w_hh,
    const float* __restrict__ b_ih,
    const float* __restrict__ b_hh,
    const float* __restrict__ w_gate,
    const float* __restrict__ b_gate,
    const float* __restrict__ w_map,
    const float* __restrict__ w_mu,
    const float* __restrict__ b_mu,
    const float* __restrict__ w_std,
    const float* __restrict__ b_std,
    float* __restrict__ out)
{
    extern __shared__ __align__(128) float smem[];
    float* wb    = smem + OFF_WB;
    float* agg_s = smem + OFF_AGG;
    float* h_s   = smem + OFF_H;
    float* wih_s = smem + OFF_WIH;
    float* adj_s = smem + OFF_ADJ;
    int*   nt_s  = (int*)(smem + OFF_NT);

    const u32 wbu      = s2u(wb);
    const u32 mb_full  = s2u(smem + OFF_MBAR);        // 3 full barriers
    const u32 mb_empty = mb_full + NBUF * 8;          // 3 empty barriers

    const int tid = threadIdx.x;       // 0..1023
    const int j   = tid & 255;         // hidden column
    const int hb  = (tid >> 8) * 4;    // 4 batches per thread
    const int b0  = blockIdx.x * TB;

    const float bihr = b_ih[j], bihz = b_ih[j + HH], bihn = b_ih[j + 2 * HH];
    const float bhhr = b_hh[j], bhhz = b_hh[j + HH], bhhn = b_hh[j + 2 * HH];
    const float bg   = b_gate[j];

    if (tid == 0) {
        #pragma unroll
        for (int i = 0; i < NBUF; i++) {
            mbar_init(mb_full + i * 8, 1);
            mbar_init(mb_empty + i * 8, NTHR);
        }
    }
    // stage w_ih into smem once (persistent)
    for (int idx = tid; idx < 10 * H3; idx += NTHR) wih_s[idx] = w_ih[idx];
    __syncthreads();

    // prime ring: stream positions 0..NBUF-1 into buffers 0..NBUF-1
    if (tid == 0) {
        #pragma unroll
        for (int p = 0; p < NBUF; p++) issue_copy(p, p, wbu, mb_full, w_hh, w_gate, w_map);
    }

    // round-robin ring cursor, uniform across all threads
    int cur_buf = 0;
    u32 cur_par = 0;
    int cur_pos = 0;

    for (int v = 0; v < NN; v++) {
        // ---- adj column v + node types ----
        if (tid < TB * NN) {
            int b = tid >> 5, n = tid & 31;
            adj_s[tid] = g_adjt[((b0 + b) << 10) + (v << 5) + n];
        }
        if (tid < TB) nt_s[tid] = node_types[(b0 + tid) * NN + v];

        float acc[4];
        #pragma unroll
        for (int b = 0; b < 4; b++) acc[b] = 0.0f;

        __syncthreads();   // BAR 1: adj_s / nt_s

        // ---- Phase A: agg = sum_n adj * gm ----
        for (int n = 0; n < v; n++) {
            float a[4];
            #pragma unroll
            for (int b = 0; b < 4; b++) a[b] = adj_s[(hb + b) * NN + n];
            float s = a[0] + a[1] + a[2] + a[3];
            if (s != 0.0f) {
                #pragma unroll
                for (int b = 0; b < 4; b++) {
                    acc[b] = fmaf(a[b],
                                  g_gm[(size_t)((b0 + hb + b) * NN + n) * HH + j],
                                  acc[b]);
                }
            }
        }
        *(float4*)(agg_s + j * PAD + hb) = make_float4(acc[0], acc[1], acc[2], acc[3]);
        __syncthreads();   // BAR 2: agg_s

        // ---- Phase B: gh = agg @ w_hh, ring-streamed weights ----
        u64 ar2[2], az2[2], an2[2];
        #pragma unroll
        for (int i = 0; i < 2; i++) { ar2[i] = 0ull; az2[i] = 0ull; an2[i] = 0ull; }

        for (int c = 0; c < NCH; c++) {
            const int buf = cur_buf;
            const u32 par = cur_par;
            mbar_wait(mb_full + buf * 8, par);
            const float* W = wb + buf * WB_FLOATS;
            #pragma unroll 8
            for (int kk = 0; kk < CHUNK; kk++) {
                const int k = c * CHUNK + kk;
                const u64 wr2 = pack2(W[kk * H3 + j]);
                const u64 wz2 = pack2(W[kk * H3 + HH + j]);
                const u64 wn2 = pack2(W[kk * H3 + 2 * HH + j]);
                const ulonglong2 q = *(const ulonglong2*)(agg_s + k * PAD + hb);
                ffma2(ar2[0], q.x, wr2); ffma2(ar2[1], q.y, wr2);
                ffma2(az2[0], q.x, wz2); ffma2(az2[1], q.y, wz2);
                ffma2(an2[0], q.x, wn2); ffma2(an2[1], q.y, wn2);
            }
            mbar_arrive(mb_empty + buf * 8);
            if (tid == 0 && cur_pos + NBUF < TOTAL_POS) {
                mbar_wait(mb_empty + buf * 8, par);
                issue_copy(cur_pos + NBUF, buf, wbu, mb_full, w_hh, w_gate, w_map);
            }
            cur_pos++;
            if (++cur_buf == NBUF) { cur_buf = 0; cur_par ^= 1; }
        }

        // ---- GRU elementwise (x@w_ih one-hot lookup from smem) ----
        {
            float hval[4];
            #pragma unroll
            for (int i = 0; i < 2; i++) {
                const float2 fr = unpack2(ar2[i]);
                const float2 fz = unpack2(az2[i]);
                const float2 fn = unpack2(an2[i]);
                #pragma unroll
                for (int u = 0; u < 2; u++) {
                    const int b = 2 * i + u;
                    const int t = nt_s[hb + b];
                    const float gir = wih_s[t * H3 + j]          + bihr;
                    const float giz = wih_s[t * H3 + HH + j]     + bihz;
                    const float gin = wih_s[t * H3 + 2 * HH + j] + bihn;
                    const float arv = u ? fr.y : fr.x;
                    const float azv = u ? fz.y : fz.x;
                    const float anv = u ? fn.y : fn.x;
                    const float r   = fsig(gir + arv + bhhr);
                    const float z   = fsig(giz + azv + bhhz);
                    const float nn_ = ftanh(gin + r * (anv + bhhn));
                    hval[b] = (1.0f - z) * nn_ + z * acc[b];
                }
            }
            *(float4*)(h_s + j * PAD + hb) = make_float4(hval[0], hval[1], hval[2], hval[3]);
        }
        __syncthreads();   // BAR 3: h_s

        if (v < NN - 1) {
            // ---- Phase C: gm_v = sigmoid(h@w_gate+bg) * (h@w_map) ----
            u64 ag2[2], am2[2];
            #pragma unroll
            for (int i = 0; i < 2; i++) { ag2[i] = 0ull; am2[i] = 0ull; }

            for (int c = 0; c < NCH; c++) {
                const int buf = cur_buf;
                const u32 par = cur_par;
                mbar_wait(mb_full + buf * 8, par);
                const float* W = wb + buf * WB_FLOATS;
                #pragma unroll 8
                for (int kk = 0; kk < CHUNK; kk++) {
                    const int k = c * CHUNK + kk;
                    const u64 wg2 = pack2(W[kk * HH + j]);
                    const u64 wm2 = pack2(W[GC_FLOATS + kk * HH + j]);
                    const ulonglong2 q = *(const ulonglong2*)(h_s + k * PAD + hb);
                    ffma2(ag2[0], q.x, wg2); ffma2(ag2[1], q.y, wg2);
                    ffma2(am2[0], q.x, wm2); ffma2(am2[1], q.y, wm2);
                }
                mbar_arrive(mb_empty + buf * 8);
                if (tid == 0 && cur_pos + NBUF < TOTAL_POS) {
                    mbar_wait(mb_empty + buf * 8, par);
                    issue_copy(cur_pos + NBUF, buf, wbu, mb_full, w_hh, w_gate, w_map);
                }
                cur_pos++;
                if (++cur_buf == NBUF) { cur_buf = 0; cur_par ^= 1; }
            }

            #pragma unroll
            for (int i = 0; i < 2; i++) {
                const float2 fg = unpack2(ag2[i]);
                const float2 fm = unpack2(am2[i]);
                const int ba = hb + 2 * i;
                g_gm[(size_t)((b0 + ba)     * NN + v) * HH + j] = fsig(fg.x + bg) * fm.x;
                g_gm[(size_t)((b0 + ba + 1) * NN + v) * HH + j] = fsig(fg.y + bg) * fm.y;
            }
        } else {
            // ---- Final: mu = h31@w_mu+b_mu ; sigma = h31@w_std+b_std ----
            const int z  = tid & 63;
            const int bb = tid >> 6;    // 0..15: one batch per 64-thread group
            float am0 = 0.f, as0 = 0.f;
            #pragma unroll 4
            for (int k = 0; k < HH; k++) {
                const float wm = w_mu[k * ZZ + z];
                const float ws = w_std[k * ZZ + z];
                const float h0 = h_s[k * PAD + bb];
                am0 = fmaf(h0, wm, am0);
                as0 = fmaf(h0, ws, as0);
            }
            out[(size_t)(b0 + bb) * ZZ + z]                   = am0 + b_mu[z];
            out[(size_t)BB * ZZ + (size_t)(b0 + bb) * ZZ + z] = as0 + b_std[z];
        }
    }
}

extern "C" void kernel_launch(void* const* d_in, const int* in_sizes, int n_in,
                              void* d_out, int out_size) {
    const float* adj        = (const float*)d_in[0];
    const int*   node_types = (const int*)  d_in[1];
    const float* w_ih       = (const float*)d_in[2];
    const float* w_hh       = (const float*)d_in[3];
    const float* b_ih       = (const float*)d_in[4];
    const float* b_hh       = (const float*)d_in[5];
    const float* w_gate     = (const float*)d_in[6];
    const float* b_gate     = (const float*)d_in[7];
    const float* w_map      = (const float*)d_in[8];
    const float* w_mu       = (const float*)d_in[9];
    const float* b_mu       = (const float*)d_in[10];
    const float* w_std      = (const float*)d_in[11];
    const float* b_std      = (const float*)d_in[12];
    float* out = (float*)d_out;

    cudaFuncSetAttribute(logicvae_main,
                         cudaFuncAttributeMaxDynamicSharedMemorySize, SMEM_BYTES);

    transpose_adj_kernel<<<(BB * NN * NN + 255) / 256, 256>>>(adj);

    logicvae_main<<<NCTA, NTHR, SMEM_BYTES>>>(node_types, w_ih, w_hh, b_ih, b_hh,
                                              w_gate, b_gate, w_map,
                                              w_mu, b_mu, w_std, b_std, out);
}

// round 15
// speedup vs baseline: 1.0013x; 1.0013x over previous
#include <cuda_runtime.h>
#include <cuda_bf16.h>
#include <cstdint>
#include <math.h>

#define BB 2048
#define NN 32
#define HH 256
#define H3 768
#define ZZ 64
#define TB 16
#define NCTA (BB / TB)   // 128
#define NTHR 1024
#define PAD 20
#define CHUNK 16
#define NBUF 3
#define NCH (HH / CHUNK)             // 16 chunks per segment
#define WB_FLOATS (CHUNK * H3)       // 12288 floats = 49152 B
#define WB_BYTES  (WB_FLOATS * 4)
#define GC_FLOATS (CHUNK * HH)       // 4096 floats = 16384 B
#define GC_BYTES  (GC_FLOATS * 4)
#define TOTAL_POS (63 * 16)          // interleaved B/C chunk stream (16 chunks/segment)

// dynamic smem layout (floats)
#define OFF_WB    0
#define OFF_AGG   (OFF_WB + NBUF * WB_FLOATS)     // 36864
#define OFF_H     (OFF_AGG + HH * PAD)
#define OFF_WIH   (OFF_H + HH * PAD)
#define OFF_ADJ   (OFF_WIH + 10 * H3)
#define OFF_NT    (OFF_ADJ + TB * NN)
#define OFF_MBAR  (OFF_NT + TB)                   // even float count -> 8B aligned
#define SMEM_BYTES ((OFF_MBAR + 16) * 4 + 64)     // ~216 KB

__device__ float g_gm[BB * NN * HH];      // 64 MB
__device__ float g_adjt[BB * NN * NN];    // 8 MB

typedef unsigned long long u64;
typedef unsigned int u32;

__device__ __forceinline__ u64 pack2(float x) {
    u64 r; asm("mov.b64 %0, {%1, %1};" : "=l"(r) : "f"(x)); return r;
}
__device__ __forceinline__ void ffma2(u64 &d, u64 a, u64 b) {
    asm("fma.rn.f32x2 %0, %1, %2, %0;" : "+l"(d) : "l"(a), "l"(b));
}
__device__ __forceinline__ float2 unpack2(u64 a) {
    float2 f; asm("mov.b64 {%0, %1}, %2;" : "=f"(f.x), "=f"(f.y) : "l"(a)); return f;
}
__device__ __forceinline__ float fsig(float x) {
    return __fdividef(1.0f, 1.0f + __expf(-x));
}
__device__ __forceinline__ float ftanh(float x) {
    float y; asm("tanh.approx.f32 %0, %1;" : "=f"(y) : "f"(x)); return y;
}
__device__ __forceinline__ u32 s2u(const void* p) {
    u32 a;
    asm("{ .reg .u64 t; cvta.to.shared.u64 t, %1; cvt.u32.u64 %0, t; }" : "=r"(a) : "l"(p));
    return a;
}
__device__ __forceinline__ void mbar_init(u32 mb, u32 cnt) {
    asm volatile("mbarrier.init.shared.b64 [%0], %1;" :: "r"(mb), "r"(cnt) : "memory");
}
__device__ __forceinline__ void mbar_expect(u32 mb, u32 bytes) {
    asm volatile("mbarrier.arrive.expect_tx.shared.b64 _, [%0], %1;" :: "r"(mb), "r"(bytes) : "memory");
}
__device__ __forceinline__ void mbar_arrive(u32 mb) {
    asm volatile("mbarrier.arrive.release.cta.shared::cta.b64 _, [%0];" :: "r"(mb) : "memory");
}
__device__ __forceinline__ void bulk_cp(u32 dst, const void* src, u32 bytes, u32 mb) {
    asm volatile("cp.async.bulk.shared::cta.global.mbarrier::complete_tx::bytes [%0], [%1], %2, [%3];"
                 :: "r"(dst), "l"(src), "r"(bytes), "r"(mb) : "memory");
}
__device__ __forceinline__ void mbar_wait(u32 mb, u32 parity) {
    asm volatile("{\n\t"
                 ".reg .pred P;\n"
                 "WL%=:\n\t"
                 "mbarrier.try_wait.parity.acquire.cta.shared::cta.b64 P, [%0], %1;\n\t"
                 "@!P bra WL%=;\n\t"
                 "}" :: "r"(mb), "r"(parity) : "memory");
}

__global__ void transpose_adj_kernel(const float* __restrict__ adj) {
    int idx = blockIdx.x * blockDim.x + threadIdx.x;
    if (idx < BB * NN * NN) {
        int b = idx >> 10;
        int r = idx & 1023;
        int v = r >> 5;
        int n = r & 31;
        g_adjt[idx] = adj[(b << 10) + (n << 5) + v];
    }
}

// issue the TMA copy for global stream position `pos` into buffer `buf`
__device__ __forceinline__ void issue_copy(
    int pos, int buf, u32 wbu, u32 mb_full_base,
    const float* __restrict__ w_hh,
    const float* __restrict__ w_gate,
    const float* __restrict__ w_map)
{
    const int seg = pos >> 4;            // 16 chunks per segment
    const int rem = pos & 15;
    const u32 dst = wbu + (u32)buf * WB_BYTES;
    const u32 mb  = mb_full_base + (u32)buf * 8;
    if (seg & 1) {   // C segment: gate + map chunk
        mbar_expect(mb, 2 * GC_BYTES);
        bulk_cp(dst, w_gate + rem * GC_FLOATS, GC_BYTES, mb);
        bulk_cp(dst + GC_BYTES, w_map + rem * GC_FLOATS, GC_BYTES, mb);
    } else {         // B segment: w_hh chunk
        mbar_expect(mb, WB_BYTES);
        bulk_cp(dst, w_hh + rem * WB_FLOATS, WB_BYTES, mb);
    }
}

__global__ __launch_bounds__(NTHR, 1) void logicvae_main(
    const int*   __restrict__ node_types,
    const float* __restrict__ w_ih,
    const float* __restrict__ w_hh,
    const float* __restrict__ b_ih,
    const float* __restrict__ b_hh,
    const float* __restrict__ w_gate,
    const float* __restrict__ b_gate,
    const float* __restrict__ w_map,
    const float* __restrict__ w_mu,
    const float* __restrict__ b_mu,
    const float* __restrict__ w_std,
    const float* __restrict__ b_std,
    float* __restrict__ out)
{
    extern __shared__ __align__(128) float smem[];
    float* wb    = smem + OFF_WB;
    float* agg_s = smem + OFF_AGG;
    float* h_s   = smem + OFF_H;
    float* wih_s = smem + OFF_WIH;
    float* adj_s = smem + OFF_ADJ;
    int*   nt_s  = (int*)(smem + OFF_NT);

    const u32 wbu      = s2u(wb);
    const u32 mb_full  = s2u(smem + OFF_MBAR);        // 3 full barriers
    const u32 mb_empty = mb_full + NBUF * 8;          // 3 empty barriers

    const int tid = threadIdx.x;       // 0..1023
    const int j   = tid & 255;         // hidden column
    const int hb  = (tid >> 8) * 4;    // 4 batches per thread
    const int b0  = blockIdx.x * TB;

    const float bihr = b_ih[j], bihz = b_ih[j + HH], bihn = b_ih[j + 2 * HH];
    const float bhhr = b_hh[j], bhhz = b_hh[j + HH], bhhn = b_hh[j + 2 * HH];
    const float bg   = b_gate[j];

    if (tid == 0) {
        #pragma unroll
        for (int i = 0; i < NBUF; i++) {
            mbar_init(mb_full + i * 8, 1);
            mbar_init(mb_empty + i * 8, NTHR);
        }
    }
    // stage w_ih into smem once (persistent)
    for (int idx = tid; idx < 10 * H3; idx += NTHR) wih_s[idx] = w_ih[idx];
    __syncthreads();

    // prime ring: stream positions 0..NBUF-1 into buffers 0..NBUF-1
    if (tid == 0) {
        #pragma unroll
        for (int p = 0; p < NBUF; p++) issue_copy(p, p, wbu, mb_full, w_hh, w_gate, w_map);
    }

    // round-robin ring cursor, uniform across all threads
    int cur_buf = 0;
    u32 cur_par = 0;
    int cur_pos = 0;

    for (int v = 0; v < NN; v++) {
        // ---- adj column v + node types ----
        if (tid < TB * NN) {
            int b = tid >> 5, n = tid & 31;
            adj_s[tid] = g_adjt[((b0 + b) << 10) + (v << 5) + n];
        }
        if (tid < TB) nt_s[tid] = node_types[(b0 + tid) * NN + v];

        float acc[4];
        #pragma unroll
        for (int b = 0; b < 4; b++) acc[b] = 0.0f;

        __syncthreads();   // BAR 1: adj_s / nt_s

        // ---- Phase A: agg = sum_n adj * gm ----
        for (int n = 0; n < v; n++) {
            float a[4];
            #pragma unroll
            for (int b = 0; b < 4; b++) a[b] = adj_s[(hb + b) * NN + n];
            float s = a[0] + a[1] + a[2] + a[3];
            if (s != 0.0f) {
                #pragma unroll
                for (int b = 0; b < 4; b++) {
                    acc[b] = fmaf(a[b],
                                  g_gm[(size_t)((b0 + hb + b) * NN + n) * HH + j],
                                  acc[b]);
                }
            }
        }
        *(float4*)(agg_s + j * PAD + hb) = make_float4(acc[0], acc[1], acc[2], acc[3]);
        __syncthreads();   // BAR 2: agg_s

        // ---- Phase B: gh = agg @ w_hh, ring-streamed weights ----
        u64 ar2[2], az2[2], an2[2];
        #pragma unroll
        for (int i = 0; i < 2; i++) { ar2[i] = 0ull; az2[i] = 0ull; an2[i] = 0ull; }

        for (int c = 0; c < NCH; c++) {
            const int buf = cur_buf;
            const u32 par = cur_par;
            mbar_wait(mb_full + buf * 8, par);
            const float* W = wb + buf * WB_FLOATS;
            #pragma unroll 8
            for (int kk = 0; kk < CHUNK; kk++) {
                const int k = c * CHUNK + kk;
                const u64 wr2 = pack2(W[kk * H3 + j]);
                const u64 wz2 = pack2(W[kk * H3 + HH + j]);
                const u64 wn2 = pack2(W[kk * H3 + 2 * HH + j]);
                const ulonglong2 q = *(const ulonglong2*)(agg_s + k * PAD + hb);
                ffma2(ar2[0], q.x, wr2); ffma2(ar2[1], q.y, wr2);
                ffma2(az2[0], q.x, wz2); ffma2(az2[1], q.y, wz2);
                ffma2(an2[0], q.x, wn2); ffma2(an2[1], q.y, wn2);
            }
            mbar_arrive(mb_empty + buf * 8);
            if (tid == 0 && cur_pos + NBUF < TOTAL_POS) {
                mbar_wait(mb_empty + buf * 8, par);
                issue_copy(cur_pos + NBUF, buf, wbu, mb_full, w_hh, w_gate, w_map);
            }
            cur_pos++;
            if (++cur_buf == NBUF) { cur_buf = 0; cur_par ^= 1; }
        }

        // ---- GRU elementwise (x@w_ih one-hot lookup from smem) ----
        {
            float hval[4];
            #pragma unroll
            for (int i = 0; i < 2; i++) {
                const float2 fr = unpack2(ar2[i]);
                const float2 fz = unpack2(az2[i]);
                const float2 fn = unpack2(an2[i]);
                #pragma unroll
                for (int u = 0; u < 2; u++) {
                    const int b = 2 * i + u;
                    const int t = nt_s[hb + b];
                    const float gir = wih_s[t * H3 + j]          + bihr;
                    const float giz = wih_s[t * H3 + HH + j]     + bihz;
                    const float gin = wih_s[t * H3 + 2 * HH + j] + bihn;
                    const float arv = u ? fr.y : fr.x;
                    const float azv = u ? fz.y : fz.x;
                    const float anv = u ? fn.y : fn.x;
                    const float r   = fsig(gir + arv + bhhr);
                    const float z   = fsig(giz + azv + bhhz);
                    const float nn_ = ftanh(gin + r * (anv + bhhn));
                    hval[b] = (1.0f - z) * nn_ + z * acc[b];
                }
            }
            *(float4*)(h_s + j * PAD + hb) = make_float4(hval[0], hval[1], hval[2], hval[3]);
        }
        __syncthreads();   // BAR 3: h_s

        if (v < NN - 1) {
            // ---- Phase C: gm_v = sigmoid(h@w_gate+bg) * (h@w_map) ----
            u64 ag2[2], am2[2];
            #pragma unroll
            for (int i = 0; i < 2; i++) { ag2[i] = 0ull; am2[i] = 0ull; }

            for (int c = 0; c < NCH; c++) {
                const int buf = cur_buf;
                const u32 par = cur_par;
                mbar_wait(mb_full + buf * 8, par);
                const float* W = wb + buf * WB_FLOATS;
                #pragma unroll 8
                for (int kk = 0; kk < CHUNK; kk++) {
                    const int k = c * CHUNK + kk;
                    const u64 wg2 = pack2(W[kk * HH + j]);
                    const u64 wm2 = pack2(W[GC_FLOATS + kk * HH + j]);
                    const ulonglong2 q = *(const ulonglong2*)(h_s + k * PAD + hb);
                    ffma2(ag2[0], q.x, wg2); ffma2(ag2[1], q.y, wg2);
                    ffma2(am2[0], q.x, wm2); ffma2(am2[1], q.y, wm2);
                }
                mbar_arrive(mb_empty + buf * 8);
                if (tid == 0 && cur_pos + NBUF < TOTAL_POS) {
                    mbar_wait(mb_empty + buf * 8, par);
                    issue_copy(cur_pos + NBUF, buf, wbu, mb_full, w_hh, w_gate, w_map);
                }
                cur_pos++;
                if (++cur_buf == NBUF) { cur_buf = 0; cur_par ^= 1; }
            }

            #pragma unroll
            for (int i = 0; i < 2; i++) {
                const float2 fg = unpack2(ag2[i]);
                const float2 fm = unpack2(am2[i]);
                const int ba = hb + 2 * i;
                g_gm[(size_t)((b0 + ba)     * NN + v) * HH + j] = fsig(fg.x + bg) * fm.x;
                g_gm[(size_t)((b0 + ba + 1) * NN + v) * HH + j] = fsig(fg.y + bg) * fm.y;
            }
        } else {
            // ---- Final: mu = h31@w_mu+b_mu ; sigma = h31@w_std+b_std ----
            const int z  = tid & 63;
            const int bb = tid >> 6;    // 0..15: one batch per 64-thread group
            float am0 = 0.f, as0 = 0.f;
            #pragma unroll 4
            for (int k = 0; k < HH; k++) {
                const float wm = w_mu[k * ZZ + z];
                const float ws = w_std[k * ZZ + z];
                const float h0 = h_s[k * PAD + bb];
                am0 = fmaf(h0, wm, am0);
                as0 = fmaf(h0, ws, as0);
            }
            out[(size_t)(b0 + bb) * ZZ + z]                   = am0 + b_mu[z];
            out[(size_t)BB * ZZ + (size_t)(b0 + bb) * ZZ + z] = as0 + b_std[z];
        }
    }
}

extern "C" void kernel_launch(void* const* d_in, const int* in_sizes, int n_in,
                              void* d_out, int out_size) {
    const float* adj        = (const float*)d_in[0];
    const int*   node_types = (const int*)  d_in[1];
    const float* w_ih       = (const float*)d_in[2];
    const float* w_hh       = (const float*)d_in[3];
    const float* b_ih       = (const float*)d_in[4];
    const float* b_hh       = (const float*)d_in[5];
    const float* w_gate     = (const float*)d_in[6];
    const float* b_gate     = (const float*)d_in[7];
    const float* w_map      = (const float*)d_in[8];
    const float* w_mu       = (const float*)d_in[9];
    const float* b_mu       = (const float*)d_in[10];
    const float* w_std      = (const float*)d_in[11];
    const float* b_std      = (const float*)d_in[12];
    float* out = (float*)d_out;

    cudaFuncSetAttribute(logicvae_main,
                         cudaFuncAttributeMaxDynamicSharedMemorySize, SMEM_BYTES);

    transpose_adj_kernel<<<(BB * NN * NN + 255) / 256, 256>>>(adj);

    logicvae_main<<<NCTA, NTHR, SMEM_BYTES>>>(node_types, w_ih, w_hh, b_ih, b_hh,
                                              w_gate, b_gate, w_map,
                                              w_mu, b_mu, w_std, b_std, out);
}

// round 16
// speedup vs baseline: 2.2365x; 2.2336x over previous
#include <cuda_runtime.h>
#include <cuda_bf16.h>
#include <cstdint>
#include <math.h>

#define BB 2048
#define NN 32
#define HH 256
#define H3 768
#define ZZ 64
#define TB 16
#define NCTA 128
#define NTHR 512
#define PAD 20
#define AP 132   // packed activation pitch (u32 per 16-batch row)

// dynamic smem offsets (floats)
#define OFF_AGG 0
#define OFF_H   (OFF_AGG + HH * PAD)      // 5120
#define OFF_WIH (OFF_H + HH * PAD)        // 10240
#define OFF_BIH (OFF_WIH + 10 * H3)       // 17920
#define OFF_BHH (OFF_BIH + H3)            // 18688
#define OFF_BG  (OFF_BHH + H3)            // 19456
#define OFF_ADJ (OFF_BG + HH)             // 19712
#define OFF_NT  (OFF_ADJ + TB * NN)       // 20224
#define OFF_AHI (OFF_NT + TB)             // 20240
#define OFF_ALO (OFF_AHI + TB * AP)       // 22352
#define SMEM_FLOATS (OFF_ALO + TB * AP)   // 24464
#define SMEM_BYTES (SMEM_FLOATS * 4)

typedef unsigned int u32;

__device__ float g_gm[BB * NN * HH];        // fp32 messages
__device__ float g_adjt[BB * NN * NN];
__device__ uint4 g_wpB[96 * 16 * 32];       // w_hh fragment-packed
__device__ uint4 g_wpC[64 * 16 * 32];       // [gate|map] fragment-packed

__device__ __forceinline__ float fsig(float x) {
    return __fdividef(1.0f, 1.0f + __expf(-x));
}
__device__ __forceinline__ float ftanh(float x) {
    float y; asm("tanh.approx.f32 %0, %1;" : "=f"(y) : "f"(x)); return y;
}
__device__ __forceinline__ u32 phx(float v0, float v1) {   // bf16 hi pair
    return (__float_as_uint(v0) >> 16) | (__float_as_uint(v1) & 0xffff0000u);
}
__device__ __forceinline__ u32 plx(float v0, float v1) {   // bf16 lo pair
    float h0 = __uint_as_float(__float_as_uint(v0) & 0xffff0000u);
    float h1 = __uint_as_float(__float_as_uint(v1) & 0xffff0000u);
    return (__float_as_uint(v0 - h0) >> 16) | (__float_as_uint(v1 - h1) & 0xffff0000u);
}
__device__ __forceinline__ void mma_bf(float* d, u32 a0, u32 a1, u32 a2, u32 a3,
                                       u32 b0, u32 b1) {
    asm("mma.sync.aligned.m16n8k16.row.col.f32.bf16.bf16.f32 "
        "{%0,%1,%2,%3},{%4,%5,%6,%7},{%8,%9},{%0,%1,%2,%3};"
        : "+f"(d[0]), "+f"(d[1]), "+f"(d[2]), "+f"(d[3])
        : "r"(a0), "r"(a1), "r"(a2), "r"(a3), "r"(b0), "r"(b1));
}

__global__ void transpose_adj_kernel(const float* __restrict__ adj) {
    int idx = blockIdx.x * blockDim.x + threadIdx.x;
    if (idx < BB * NN * NN) {
        int b = idx >> 10, r = idx & 1023, v = r >> 5, n = r & 31;
        g_adjt[idx] = adj[(b << 10) + (n << 5) + v];
    }
}

__global__ void prep_wpB(const float* __restrict__ w_hh) {
    int idx = blockIdx.x * blockDim.x + threadIdx.x;
    if (idx >= 96 * 16 * 32) return;
    int lane = idx & 31, ks = (idx >> 5) & 15, tile = idx >> 9;
    int n  = tile * 8 + (lane >> 2);
    int k0 = ks * 16 + 2 * (lane & 3);
    float v00 = w_hh[k0 * H3 + n],       v01 = w_hh[(k0 + 1) * H3 + n];
    float v10 = w_hh[(k0 + 8) * H3 + n], v11 = w_hh[(k0 + 9) * H3 + n];
    g_wpB[idx] = make_uint4(phx(v00, v01), phx(v10, v11), plx(v00, v01), plx(v10, v11));
}

__global__ void prep_wpC(const float* __restrict__ w_gate,
                         const float* __restrict__ w_map) {
    int idx = blockIdx.x * blockDim.x + threadIdx.x;
    if (idx >= 64 * 16 * 32) return;
    int lane = idx & 31, ks = (idx >> 5) & 15, tile = idx >> 9;
    int cg = lane >> 2;
    int k0 = ks * 16 + 2 * (lane & 3);
    const float* W = (tile < 32) ? w_gate : w_map;
    int n = ((tile < 32) ? tile : tile - 32) * 8 + cg;
    float v00 = W[k0 * HH + n],       v01 = W[(k0 + 1) * HH + n];
    float v10 = W[(k0 + 8) * HH + n], v11 = W[(k0 + 9) * HH + n];
    g_wpC[idx] = make_uint4(phx(v00, v01), phx(v10, v11), plx(v00, v01), plx(v10, v11));
}

__global__ __launch_bounds__(NTHR, 1) void logicvae_main(
    const int*   __restrict__ node_types,
    const float* __restrict__ w_ih,
    const float* __restrict__ b_ih,
    const float* __restrict__ b_hh,
    const float* __restrict__ b_gate,
    const float* __restrict__ w_mu,
    const float* __restrict__ b_mu,
    const float* __restrict__ w_std,
    const float* __restrict__ b_std,
    float* __restrict__ out)
{
    extern __shared__ __align__(128) float smem[];
    float* agg_s = smem + OFF_AGG;     // [j][PAD] fp32
    float* h_s   = smem + OFF_H;       // [j][PAD] fp32
    float* wih_s = smem + OFF_WIH;
    float* bih_s = smem + OFF_BIH;
    float* bhh_s = smem + OFF_BHH;
    float* bg_s  = smem + OFF_BG;
    float* adj_s = smem + OFF_ADJ;
    int*   nt_s  = (int*)(smem + OFF_NT);
    u32*   ahi   = (u32*)(smem + OFF_AHI);   // [16][AP]
    u32*   alo   = (u32*)(smem + OFF_ALO);

    const int tid  = threadIdx.x;      // 0..511
    const int j    = tid & 255;
    const int hb   = (tid >> 8) * 8;
    const int b0   = blockIdx.x * TB;
    const int w    = tid >> 5;         // warp 0..15
    const int lane = tid & 31;
    const int fr   = lane >> 2;        // fragment row/col group
    const int ft   = lane & 3;

    for (int idx = tid; idx < 10 * H3; idx += NTHR) wih_s[idx] = w_ih[idx];
    for (int idx = tid; idx < H3; idx += NTHR) { bih_s[idx] = b_ih[idx]; bhh_s[idx] = b_hh[idx]; }
    if (tid < HH) bg_s[tid] = b_gate[tid];
    __syncthreads();

    for (int v = 0; v < NN; v++) {
        // ---- adj column v + node types ----
        {
            int b = tid >> 5, n = tid & 31;
            adj_s[tid] = g_adjt[((b0 + b) << 10) + (v << 5) + n];
        }
        if (tid < TB) nt_s[tid] = node_types[(b0 + tid) * NN + v];
        __syncthreads();   // also fences previous step's g_gm writes

        // ---- Phase A (fp32): agg = sum_n adj * gm ----
        {
            float acc[8];
            #pragma unroll
            for (int b = 0; b < 8; b++) acc[b] = 0.0f;
            for (int n = 0; n < v; n++) {
                float a[8];
                #pragma unroll
                for (int b = 0; b < 8; b++) a[b] = adj_s[(hb + b) * NN + n];
                float s = a[0]+a[1]+a[2]+a[3]+a[4]+a[5]+a[6]+a[7];
                if (s != 0.0f) {
                    #pragma unroll
                    for (int b = 0; b < 8; b++)
                        acc[b] = fmaf(a[b], g_gm[(size_t)((b0 + hb + b) * NN + n) * HH + j], acc[b]);
                }
            }
            float4* a4 = (float4*)(agg_s + j * PAD + hb);
            a4[0] = make_float4(acc[0], acc[1], acc[2], acc[3]);
            a4[1] = make_float4(acc[4], acc[5], acc[6], acc[7]);
        }
        __syncthreads();

        // ---- pack agg -> bf16 hi/lo fragment arrays ----
        for (int idx = tid; idx < TB * 128; idx += NTHR) {
            int b = idx >> 7, cp = idx & 127;
            float v0 = agg_s[(2 * cp) * PAD + b];
            float v1 = agg_s[(2 * cp + 1) * PAD + b];
            ahi[b * AP + cp] = phx(v0, v1);
            alo[b * AP + cp] = plx(v0, v1);
        }
        __syncthreads();

        // ---- Phase B: gh = agg @ w_hh via mma (6 tiles per warp) ----
        float d0[4]={0,0,0,0}, d1[4]={0,0,0,0}, d2[4]={0,0,0,0},
              d3[4]={0,0,0,0}, d4[4]={0,0,0,0}, d5[4]={0,0,0,0};
        #pragma unroll 4
        for (int ks = 0; ks < 16; ks++) {
            const int cpb = ks * 8 + ft;
            const u32 ah0 = ahi[fr * AP + cpb],       ah1 = ahi[(fr + 8) * AP + cpb];
            const u32 ah2 = ahi[fr * AP + cpb + 4],   ah3 = ahi[(fr + 8) * AP + cpb + 4];
            const u32 al0 = alo[fr * AP + cpb],       al1 = alo[(fr + 8) * AP + cpb];
            const u32 al2 = alo[fr * AP + cpb + 4],   al3 = alo[(fr + 8) * AP + cpb + 4];
            float* ds[6] = {d0, d1, d2, d3, d4, d5};
            #pragma unroll
            for (int i = 0; i < 6; i++) {
                const uint4 wq = g_wpB[(((w + 16 * i) * 16 + ks) << 5) + lane];
                mma_bf(ds[i], ah0, ah1, ah2, ah3, wq.x, wq.y);
                mma_bf(ds[i], al0, al1, al2, al3, wq.x, wq.y);
                mma_bf(ds[i], ah0, ah1, ah2, ah3, wq.z, wq.w);
            }
        }

        // ---- GRU epilogue in fragment lanes ----
        {
            float* dr[2] = {d0, d1};
            float* dz[2] = {d2, d3};
            float* dn[2] = {d4, d5};
            #pragma unroll
            for (int m = 0; m < 2; m++) {
                const int jb = 8 * (w + 16 * m);
                #pragma unroll
                for (int di = 0; di < 4; di++) {
                    const int jj = jb + 2 * ft + (di & 1);
                    const int bb = fr + 8 * (di >> 1);
                    const int t  = nt_s[bb];
                    const float gir = wih_s[t * H3 + jj]          + bih_s[jj];
                    const float giz = wih_s[t * H3 + HH + jj]     + bih_s[HH + jj];
                    const float gin = wih_s[t * H3 + 2 * HH + jj] + bih_s[2 * HH + jj];
                    const float rg = fsig(gir + dr[m][di] + bhh_s[jj]);
                    const float zg = fsig(giz + dz[m][di] + bhh_s[HH + jj]);
                    const float ng = ftanh(gin + rg * (dn[m][di] + bhh_s[2 * HH + jj]));
                    const float av = agg_s[jj * PAD + bb];
                    h_s[jj * PAD + bb] = (1.0f - zg) * ng + zg * av;
                }
            }
        }
        __syncthreads();

        if (v < NN - 1) {
            // ---- pack h -> fragment arrays (reuse buffers) ----
            for (int idx = tid; idx < TB * 128; idx += NTHR) {
                int b = idx >> 7, cp = idx & 127;
                float v0 = h_s[(2 * cp) * PAD + b];
                float v1 = h_s[(2 * cp + 1) * PAD + b];
                ahi[b * AP + cp] = phx(v0, v1);
                alo[b * AP + cp] = plx(v0, v1);
            }
            __syncthreads();

            // ---- Phase C: [gate|map] via mma (4 tiles per warp) ----
            float e0[4]={0,0,0,0}, e1[4]={0,0,0,0}, e2[4]={0,0,0,0}, e3[4]={0,0,0,0};
            #pragma unroll 4
            for (int ks = 0; ks < 16; ks++) {
                const int cpb = ks * 8 + ft;
                const u32 ah0 = ahi[fr * AP + cpb],       ah1 = ahi[(fr + 8) * AP + cpb];
                const u32 ah2 = ahi[fr * AP + cpb + 4],   ah3 = ahi[(fr + 8) * AP + cpb + 4];
                const u32 al0 = alo[fr * AP + cpb],       al1 = alo[(fr + 8) * AP + cpb];
                const u32 al2 = alo[fr * AP + cpb + 4],   al3 = alo[(fr + 8) * AP + cpb + 4];
                float* es[4] = {e0, e1, e2, e3};
                #pragma unroll
                for (int i = 0; i < 4; i++) {
                    const uint4 wq = g_wpC[(((w + 16 * i) * 16 + ks) << 5) + lane];
                    mma_bf(es[i], ah0, ah1, ah2, ah3, wq.x, wq.y);
                    mma_bf(es[i], al0, al1, al2, al3, wq.x, wq.y);
                    mma_bf(es[i], ah0, ah1, ah2, ah3, wq.z, wq.w);
                }
            }
            {
                float* eg[2] = {e0, e1};
                float* em[2] = {e2, e3};
                #pragma unroll
                for (int m = 0; m < 2; m++) {
                    const int jb = 8 * (w + 16 * m);
                    #pragma unroll
                    for (int di = 0; di < 4; di++) {
                        const int jj = jb + 2 * ft + (di & 1);
                        const int bb = fr + 8 * (di >> 1);
                        const float g = fsig(eg[m][di] + bg_s[jj]) * em[m][di];
                        g_gm[(size_t)((b0 + bb) * NN + v) * HH + jj] = g;
                    }
                }
            }
        } else {
            // ---- Final: mu/sigma projections (fp32) ----
            const int z   = tid & 63;
            const int grp = tid >> 6;
            const int bA  = 2 * grp, bBt = 2 * grp + 1;
            float am0 = 0.f, am1 = 0.f, as0 = 0.f, as1 = 0.f;
            #pragma unroll 4
            for (int k = 0; k < HH; k++) {
                const float wm = w_mu[k * ZZ + z];
                const float ws = w_std[k * ZZ + z];
                const float h0 = h_s[k * PAD + bA];
                const float h1 = h_s[k * PAD + bBt];
                am0 = fmaf(h0, wm, am0); am1 = fmaf(h1, wm, am1);
                as0 = fmaf(h0, ws, as0); as1 = fmaf(h1, ws, as1);
            }
            const float bmu = b_mu[z], bstd = b_std[z];
            out[(size_t)(b0 + bA) * ZZ + z]  = am0 + bmu;
            out[(size_t)(b0 + bBt) * ZZ + z] = am1 + bmu;
            out[(size_t)BB * ZZ + (size_t)(b0 + bA) * ZZ + z]  = as0 + bstd;
            out[(size_t)BB * ZZ + (size_t)(b0 + bBt) * ZZ + z] = as1 + bstd;
        }
    }
}

extern "C" void kernel_launch(void* const* d_in, const int* in_sizes, int n_in,
                              void* d_out, int out_size) {
    const float* adj        = (const float*)d_in[0];
    const int*   node_types = (const int*)  d_in[1];
    const float* w_ih       = (const float*)d_in[2];
    const float* w_hh       = (const float*)d_in[3];
    const float* b_ih       = (const float*)d_in[4];
    const float* b_hh       = (const float*)d_in[5];
    const float* w_gate     = (const float*)d_in[6];
    const float* b_gate     = (const float*)d_in[7];
    const float* w_map      = (const float*)d_in[8];
    const float* w_mu       = (const float*)d_in[9];
    const float* b_mu       = (const float*)d_in[10];
    const float* w_std      = (const float*)d_in[11];
    const float* b_std      = (const float*)d_in[12];
    float* out = (float*)d_out;

    cudaFuncSetAttribute(logicvae_main,
                         cudaFuncAttributeMaxDynamicSharedMemorySize, SMEM_BYTES);

    transpose_adj_kernel<<<(BB * NN * NN + 255) / 256, 256>>>(adj);
    prep_wpB<<<(96 * 16 * 32 + 255) / 256, 256>>>(w_hh);
    prep_wpC<<<(64 * 16 * 32 + 255) / 256, 256>>>(w_gate, w_map);

    logicvae_main<<<NCTA, NTHR, SMEM_BYTES>>>(node_types, w_ih, b_ih, b_hh,
                                              b_gate, w_mu, b_mu, w_std, b_std, out);
}

// round 17
// speedup vs baseline: 2.2667x; 1.0135x over previous
#include <cuda_runtime.h>
#include <cuda_bf16.h>
#include <cstdint>
#include <math.h>

#define BB 2048
#define NN 32
#define HH 256
#define H3 768
#define ZZ 64
#define TB 16
#define NCTA 128
#define NTHR 1024
#define PAD 20
#define AP 132   // packed activation pitch (u32 per 16-batch row)

// dynamic smem offsets (floats)
#define OFF_AGG 0
#define OFF_H   (OFF_AGG + HH * PAD)      // 5120
#define OFF_WIH (OFF_H + HH * PAD)        // 10240
#define OFF_BIH (OFF_WIH + 10 * H3)       // 17920
#define OFF_BHH (OFF_BIH + H3)            // 18688
#define OFF_BG  (OFF_BHH + H3)            // 19456
#define OFF_ADJ (OFF_BG + HH)             // 19712
#define OFF_NT  (OFF_ADJ + TB * NN)       // 20224
#define OFF_AHI (OFF_NT + TB)             // 20240
#define OFF_ALO (OFF_AHI + TB * AP)       // 22352
#define SMEM_FLOATS (OFF_ALO + TB * AP)   // 24464
#define SMEM_BYTES (SMEM_FLOATS * 4)

typedef unsigned int u32;

__device__ float g_gm[BB * NN * HH];        // fp32 messages
__device__ float g_adjt[BB * NN * NN];
__device__ uint4 g_wpB[96 * 16 * 32];       // w_hh fragment-packed
__device__ uint4 g_wpC[64 * 16 * 32];       // [gate|map] fragment-packed

__device__ __forceinline__ float fsig(float x) {
    return __fdividef(1.0f, 1.0f + __expf(-x));
}
__device__ __forceinline__ float ftanh(float x) {
    float y; asm("tanh.approx.f32 %0, %1;" : "=f"(y) : "f"(x)); return y;
}
__device__ __forceinline__ u32 phx(float v0, float v1) {   // bf16 hi pair
    return (__float_as_uint(v0) >> 16) | (__float_as_uint(v1) & 0xffff0000u);
}
__device__ __forceinline__ u32 plx(float v0, float v1) {   // bf16 lo pair
    float h0 = __uint_as_float(__float_as_uint(v0) & 0xffff0000u);
    float h1 = __uint_as_float(__float_as_uint(v1) & 0xffff0000u);
    return (__float_as_uint(v0 - h0) >> 16) | (__float_as_uint(v1 - h1) & 0xffff0000u);
}
__device__ __forceinline__ void mma_bf(float* d, u32 a0, u32 a1, u32 a2, u32 a3,
                                       u32 b0, u32 b1) {
    asm("mma.sync.aligned.m16n8k16.row.col.f32.bf16.bf16.f32 "
        "{%0,%1,%2,%3},{%4,%5,%6,%7},{%8,%9},{%0,%1,%2,%3};"
        : "+f"(d[0]), "+f"(d[1]), "+f"(d[2]), "+f"(d[3])
        : "r"(a0), "r"(a1), "r"(a2), "r"(a3), "r"(b0), "r"(b1));
}

__global__ void transpose_adj_kernel(const float* __restrict__ adj) {
    int idx = blockIdx.x * blockDim.x + threadIdx.x;
    if (idx < BB * NN * NN) {
        int b = idx >> 10, r = idx & 1023, v = r >> 5, n = r & 31;
        g_adjt[idx] = adj[(b << 10) + (n << 5) + v];
    }
}

__global__ void prep_wpB(const float* __restrict__ w_hh) {
    int idx = blockIdx.x * blockDim.x + threadIdx.x;
    if (idx >= 96 * 16 * 32) return;
    int lane = idx & 31, ks = (idx >> 5) & 15, tile = idx >> 9;
    int n  = tile * 8 + (lane >> 2);
    int k0 = ks * 16 + 2 * (lane & 3);
    float v00 = w_hh[k0 * H3 + n],       v01 = w_hh[(k0 + 1) * H3 + n];
    float v10 = w_hh[(k0 + 8) * H3 + n], v11 = w_hh[(k0 + 9) * H3 + n];
    g_wpB[idx] = make_uint4(phx(v00, v01), phx(v10, v11), plx(v00, v01), plx(v10, v11));
}

__global__ void prep_wpC(const float* __restrict__ w_gate,
                         const float* __restrict__ w_map) {
    int idx = blockIdx.x * blockDim.x + threadIdx.x;
    if (idx >= 64 * 16 * 32) return;
    int lane = idx & 31, ks = (idx >> 5) & 15, tile = idx >> 9;
    int cg = lane >> 2;
    int k0 = ks * 16 + 2 * (lane & 3);
    const float* W = (tile < 32) ? w_gate : w_map;
    int n = ((tile < 32) ? tile : tile - 32) * 8 + cg;
    float v00 = W[k0 * HH + n],       v01 = W[(k0 + 1) * HH + n];
    float v10 = W[(k0 + 8) * HH + n], v11 = W[(k0 + 9) * HH + n];
    g_wpC[idx] = make_uint4(phx(v00, v01), phx(v10, v11), plx(v00, v01), plx(v10, v11));
}

__global__ __launch_bounds__(NTHR, 1) void logicvae_main(
    const int*   __restrict__ node_types,
    const float* __restrict__ w_ih,
    const float* __restrict__ b_ih,
    const float* __restrict__ b_hh,
    const float* __restrict__ b_gate,
    const float* __restrict__ w_mu,
    const float* __restrict__ b_mu,
    const float* __restrict__ w_std,
    const float* __restrict__ b_std,
    float* __restrict__ out)
{
    extern __shared__ __align__(128) float smem[];
    float* agg_s = smem + OFF_AGG;     // [j][PAD] fp32
    float* h_s   = smem + OFF_H;       // [j][PAD] fp32
    float* wih_s = smem + OFF_WIH;
    float* bih_s = smem + OFF_BIH;
    float* bhh_s = smem + OFF_BHH;
    float* bg_s  = smem + OFF_BG;
    float* adj_s = smem + OFF_ADJ;
    int*   nt_s  = (int*)(smem + OFF_NT);
    u32*   ahi   = (u32*)(smem + OFF_AHI);   // [16][AP]
    u32*   alo   = (u32*)(smem + OFF_ALO);

    const int tid  = threadIdx.x;      // 0..1023
    const int j    = tid & 255;
    const int qb   = (tid >> 8) * 4;   // 4 batches per thread in phase A
    const int b0   = blockIdx.x * TB;
    const int w    = tid >> 5;         // warp 0..31
    const int lane = tid & 31;
    const int fr   = lane >> 2;        // fragment row group
    const int ft   = lane & 3;

    for (int idx = tid; idx < 10 * H3; idx += NTHR) wih_s[idx] = w_ih[idx];
    for (int idx = tid; idx < H3; idx += NTHR) { bih_s[idx] = b_ih[idx]; bhh_s[idx] = b_hh[idx]; }
    if (tid < HH) bg_s[tid] = b_gate[tid];
    __syncthreads();

    for (int v = 0; v < NN; v++) {
        // ---- adj column v + node types ----
        if (tid < TB * NN) {
            int b = tid >> 5, n = tid & 31;
            adj_s[tid] = g_adjt[((b0 + b) << 10) + (v << 5) + n];
        }
        if (tid < TB) nt_s[tid] = node_types[(b0 + tid) * NN + v];
        __syncthreads();   // also fences previous step's g_gm writes

        // ---- Phase A (fp32): agg = sum_n adj * gm (4 batches/thread) ----
        {
            float acc[4];
            #pragma unroll
            for (int b = 0; b < 4; b++) acc[b] = 0.0f;
            for (int n = 0; n < v; n++) {
                float a[4];
                #pragma unroll
                for (int b = 0; b < 4; b++) a[b] = adj_s[(qb + b) * NN + n];
                float s = a[0] + a[1] + a[2] + a[3];
                if (s != 0.0f) {
                    #pragma unroll
                    for (int b = 0; b < 4; b++)
                        acc[b] = fmaf(a[b], g_gm[(size_t)((b0 + qb + b) * NN + n) * HH + j], acc[b]);
                }
            }
            *(float4*)(agg_s + j * PAD + qb) = make_float4(acc[0], acc[1], acc[2], acc[3]);
        }
        __syncthreads();

        // ---- pack agg -> bf16 hi/lo fragment arrays ----
        for (int idx = tid; idx < TB * 128; idx += NTHR) {
            int b = idx >> 7, cp = idx & 127;
            float v0 = agg_s[(2 * cp) * PAD + b];
            float v1 = agg_s[(2 * cp + 1) * PAD + b];
            ahi[b * AP + cp] = phx(v0, v1);
            alo[b * AP + cp] = plx(v0, v1);
        }
        __syncthreads();

        // ---- Phase B: gh = agg @ w_hh via mma (r/z/n tile per warp, same octet) ----
        float dr[4] = {0,0,0,0}, dz[4] = {0,0,0,0}, dn[4] = {0,0,0,0};
        #pragma unroll 4
        for (int ks = 0; ks < 16; ks++) {
            const int cpb = ks * 8 + ft;
            const u32 ah0 = ahi[fr * AP + cpb],       ah1 = ahi[(fr + 8) * AP + cpb];
            const u32 ah2 = ahi[fr * AP + cpb + 4],   ah3 = ahi[(fr + 8) * AP + cpb + 4];
            const u32 al0 = alo[fr * AP + cpb],       al1 = alo[(fr + 8) * AP + cpb];
            const u32 al2 = alo[fr * AP + cpb + 4],   al3 = alo[(fr + 8) * AP + cpb + 4];
            const uint4 wr = g_wpB[(((w     ) * 16 + ks) << 5) + lane];
            const uint4 wz = g_wpB[(((w + 32) * 16 + ks) << 5) + lane];
            const uint4 wn = g_wpB[(((w + 64) * 16 + ks) << 5) + lane];
            mma_bf(dr, ah0, ah1, ah2, ah3, wr.x, wr.y);
            mma_bf(dr, al0, al1, al2, al3, wr.x, wr.y);
            mma_bf(dr, ah0, ah1, ah2, ah3, wr.z, wr.w);
            mma_bf(dz, ah0, ah1, ah2, ah3, wz.x, wz.y);
            mma_bf(dz, al0, al1, al2, al3, wz.x, wz.y);
            mma_bf(dz, ah0, ah1, ah2, ah3, wz.z, wz.w);
            mma_bf(dn, ah0, ah1, ah2, ah3, wn.x, wn.y);
            mma_bf(dn, al0, al1, al2, al3, wn.x, wn.y);
            mma_bf(dn, ah0, ah1, ah2, ah3, wn.z, wn.w);
        }

        // ---- GRU epilogue in fragment lanes (one jj octet per warp) ----
        {
            #pragma unroll
            for (int di = 0; di < 4; di++) {
                const int jj = 8 * w + 2 * ft + (di & 1);
                const int bb = fr + 8 * (di >> 1);
                const int t  = nt_s[bb];
                const float gir = wih_s[t * H3 + jj]          + bih_s[jj];
                const float giz = wih_s[t * H3 + HH + jj]     + bih_s[HH + jj];
                const float gin = wih_s[t * H3 + 2 * HH + jj] + bih_s[2 * HH + jj];
                const float rg = fsig(gir + dr[di] + bhh_s[jj]);
                const float zg = fsig(giz + dz[di] + bhh_s[HH + jj]);
                const float ng = ftanh(gin + rg * (dn[di] + bhh_s[2 * HH + jj]));
                const float av = agg_s[jj * PAD + bb];
                h_s[jj * PAD + bb] = (1.0f - zg) * ng + zg * av;
            }
        }
        __syncthreads();

        if (v < NN - 1) {
            // ---- pack h -> fragment arrays (reuse buffers) ----
            for (int idx = tid; idx < TB * 128; idx += NTHR) {
                int b = idx >> 7, cp = idx & 127;
                float v0 = h_s[(2 * cp) * PAD + b];
                float v1 = h_s[(2 * cp + 1) * PAD + b];
                ahi[b * AP + cp] = phx(v0, v1);
                alo[b * AP + cp] = plx(v0, v1);
            }
            __syncthreads();

            // ---- Phase C: gate/map tile per warp (same octet) ----
            float eg[4] = {0,0,0,0}, em[4] = {0,0,0,0};
            #pragma unroll 4
            for (int ks = 0; ks < 16; ks++) {
                const int cpb = ks * 8 + ft;
                const u32 ah0 = ahi[fr * AP + cpb],       ah1 = ahi[(fr + 8) * AP + cpb];
                const u32 ah2 = ahi[fr * AP + cpb + 4],   ah3 = ahi[(fr + 8) * AP + cpb + 4];
                const u32 al0 = alo[fr * AP + cpb],       al1 = alo[(fr + 8) * AP + cpb];
                const u32 al2 = alo[fr * AP + cpb + 4],   al3 = alo[(fr + 8) * AP + cpb + 4];
                const uint4 wg = g_wpC[(((w     ) * 16 + ks) << 5) + lane];
                const uint4 wm = g_wpC[(((w + 32) * 16 + ks) << 5) + lane];
                mma_bf(eg, ah0, ah1, ah2, ah3, wg.x, wg.y);
                mma_bf(eg, al0, al1, al2, al3, wg.x, wg.y);
                mma_bf(eg, ah0, ah1, ah2, ah3, wg.z, wg.w);
                mma_bf(em, ah0, ah1, ah2, ah3, wm.x, wm.y);
                mma_bf(em, al0, al1, al2, al3, wm.x, wm.y);
                mma_bf(em, ah0, ah1, ah2, ah3, wm.z, wm.w);
            }
            #pragma unroll
            for (int di = 0; di < 4; di++) {
                const int jj = 8 * w + 2 * ft + (di & 1);
                const int bb = fr + 8 * (di >> 1);
                const float g = fsig(eg[di] + bg_s[jj]) * em[di];
                g_gm[(size_t)((b0 + bb) * NN + v) * HH + jj] = g;
            }
        } else {
            // ---- Final: mu/sigma projections (fp32), one batch per 64 threads ----
            const int z  = tid & 63;
            const int bb = tid >> 6;    // 0..15
            float am0 = 0.f, as0 = 0.f;
            #pragma unroll 4
            for (int k = 0; k < HH; k++) {
                const float wm = w_mu[k * ZZ + z];
                const float ws = w_std[k * ZZ + z];
                const float h0 = h_s[k * PAD + bb];
                am0 = fmaf(h0, wm, am0);
                as0 = fmaf(h0, ws, as0);
            }
            out[(size_t)(b0 + bb) * ZZ + z]                   = am0 + b_mu[z];
            out[(size_t)BB * ZZ + (size_t)(b0 + bb) * ZZ + z] = as0 + b_std[z];
        }
    }
}

extern "C" void kernel_launch(void* const* d_in, const int* in_sizes, int n_in,
                              void* d_out, int out_size) {
    const float* adj        = (const float*)d_in[0];
    const int*   node_types = (const int*)  d_in[1];
    const float* w_ih       = (const float*)d_in[2];
    const float* w_hh       = (const float*)d_in[3];
    const float* b_ih       = (const float*)d_in[4];
    const float* b_hh       = (const float*)d_in[5];
    const float* w_gate     = (const float*)d_in[6];
    const float* b_gate     = (const float*)d_in[7];
    const float* w_map      = (const float*)d_in[8];
    const float* w_mu       = (const float*)d_in[9];
    const float* b_mu       = (const float*)d_in[10];
    const float* w_std      = (const float*)d_in[11];
    const float* b_std      = (const float*)d_in[12];
    float* out = (float*)d_out;

    cudaFuncSetAttribute(logicvae_main,
                         cudaFuncAttributeMaxDynamicSharedMemorySize, SMEM_BYTES);

    transpose_adj_kernel<<<(BB * NN * NN + 255) / 256, 256>>>(adj);
    prep_wpB<<<(96 * 16 * 32 + 255) / 256, 256>>>(w_hh);
    prep_wpC<<<(64 * 16 * 32 + 255) / 256, 256>>>(w_gate, w_map);

    logicvae_main<<<NCTA, NTHR, SMEM_BYTES>>>(node_types, w_ih, b_ih, b_hh,
                                              b_gate, w_mu, b_mu, w_std, b_std, out);
}